// round 14
// baseline (speedup 1.0000x reference)
#include <cuda_runtime.h>
#include <cuda_fp16.h>
#include <cstdint>

// Problem constants
#define BB   2
#define TT   2048
#define HIDN 2048
#define NH   16
#define NKV  4
#define HD   128
#define BT   (BB*TT)          // 4096
#define QD   (NH*HD)          // 2048
#define KVD  (NKV*HD)         // 512
#define QKVN (QD + 2*KVD)     // 3072 (fused Q|K|V projection width)

// ---------------------------------------------------------------------------
// Scratch (allocation-free rule: __device__ globals). All-fp16 intermediates.
// ---------------------------------------------------------------------------
__device__ __half g_qkvh[(size_t)BT*QKVN];          // fp16 QKV gemm output
__device__ __half g_xh [(size_t)BT*HIDN];           // x: fp16
__device__ __half g_ah [(size_t)BT*QD];             // attention out: fp16
__device__ __half g_qh [(size_t)BT*QD];             // Q: fp16 (pre-scaled, roped)
__device__ __half g_kh [(size_t)BT*KVD];            // K: fp16 (roped)
__device__ __half g_vth[(size_t)BT*KVD];            // Vt: fp16, [b*KVD + ch][t]
__device__ __half g_wh [(size_t)QKVN*HIDN];         // rows: Wq^T | Wk^T | Wv^T
__device__ __half g_woh[(size_t)HIDN*QD];           // Wo^T

// ---------------------------------------------------------------------------
// PTX helpers (baseline PTX only — harness targets compute_103, no tcgen05)
// ---------------------------------------------------------------------------
__device__ __forceinline__ uint32_t s2u(const void* p) {
    return (uint32_t)__cvta_generic_to_shared(p);
}
__device__ __forceinline__ void cp16(uint32_t s, const void* g) {
    asm volatile("cp.async.cg.shared.global [%0], [%1], 16;" :: "r"(s), "l"(g));
}
__device__ __forceinline__ void ldsm4(uint32_t* r, uint32_t addr) {
    asm volatile("ldmatrix.sync.aligned.m8n8.x4.shared.b16 {%0,%1,%2,%3}, [%4];"
                 : "=r"(r[0]), "=r"(r[1]), "=r"(r[2]), "=r"(r[3]) : "r"(addr));
}
__device__ __forceinline__ void mma16816(float* d,
                                         const uint32_t* a, uint32_t b0, uint32_t b1) {
    asm volatile("mma.sync.aligned.m16n8k16.row.col.f32.f16.f16.f32 "
                 "{%0,%1,%2,%3}, {%4,%5,%6,%7}, {%8,%9}, {%0,%1,%2,%3};"
                 : "+f"(d[0]), "+f"(d[1]), "+f"(d[2]), "+f"(d[3])
                 : "r"(a[0]), "r"(a[1]), "r"(a[2]), "r"(a[3]), "r"(b0), "r"(b1));
}
__device__ __forceinline__ uint32_t pack2h(float v0, float v1) {
    __half2 h = __floats2half2_rn(v0, v1);
    return *reinterpret_cast<uint32_t*>(&h);
}

// ---------------------------------------------------------------------------
// Convert fp32 -> fp16, vectorized 4 elems/thread
// ---------------------------------------------------------------------------
__global__ void cvt_kernel4(const float4* __restrict__ in,
                            uint2* __restrict__ hi, int n4) {
    int i = blockIdx.x * blockDim.x + threadIdx.x;
    if (i >= n4) return;
    float4 v = in[i];
    uint2 h;
    h.x = pack2h(v.x, v.y);
    h.y = pack2h(v.z, v.w);
    hi[i] = h;
}

// ---------------------------------------------------------------------------
// Merged weight transpose: 4 matrices (Wq, Wk, Wv, Wo), all 2048 input rows.
// z selects matrix. in [2048][Ncols] fp32 -> out [Ncols][2048] fp16.
// Stores vectorized as half2 (two consecutive output columns per thread-step).
// ---------------------------------------------------------------------------
__global__ void wtrans4(const float* __restrict__ Wq, const float* __restrict__ Wk,
                        const float* __restrict__ Wv, const float* __restrict__ Wo,
                        __half* __restrict__ wh, __half* __restrict__ woh) {
    const float* in;
    __half* out;
    int Ncols;
    switch (blockIdx.z) {
        case 0:  in = Wq; out = wh;                           Ncols = QD;   break;
        case 1:  in = Wk; out = wh + (size_t)QD*HIDN;         Ncols = KVD;  break;
        case 2:  in = Wv; out = wh + (size_t)(QD+KVD)*HIDN;   Ncols = KVD;  break;
        default: in = Wo; out = woh;                          Ncols = HIDN; break;
    }
    int c0 = blockIdx.x * 32;
    if (c0 >= Ncols) return;
    int r0 = blockIdx.y * 32;
    __shared__ float t[32][33];
    int tx = threadIdx.x, ty = threadIdx.y;
    for (int i = ty; i < 32; i += 8)
        t[i][tx] = in[(size_t)(r0 + i) * Ncols + c0 + tx];
    __syncthreads();
    // each thread stores half2 along output row (r dimension contiguous)
    int tr = (tx & 15) * 2;              // output-row pair within tile
    int jc = ty + ((tx >> 4) << 3);      // output column 0..15
    for (int rep = 0; rep < 2; rep++, jc += 16) {
        __half2 v = __floats2half2_rn(t[tr][jc], t[tr + 1][jc]);
        *reinterpret_cast<__half2*>(&out[(size_t)(c0 + jc) * HIDN + r0 + tr]) = v;
    }
}

// ---------------------------------------------------------------------------
// V transpose: g_qkvh [b*TT + t][QKVN] (v at col 2560+) -> vt [b*KVD + ch][TT]
// ---------------------------------------------------------------------------
__global__ void vtrans_h(const __half* __restrict__ v,
                         __half* __restrict__ hi) {
    __shared__ float t[32][33];
    int t0 = blockIdx.x * 32, c0 = blockIdx.y * 32, b = blockIdx.z;
    int tx = threadIdx.x, ty = threadIdx.y;
    for (int i = ty; i < 32; i += 8)
        t[i][tx] = __half2float(v[((size_t)(b * TT + t0 + i)) * QKVN + QD + KVD + c0 + tx]);
    __syncthreads();
    for (int j = ty; j < 32; j += 8)
        hi[((size_t)b * KVD + c0 + j) * TT + t0 + tx] = __float2half(t[tx][j]);
}

// ---------------------------------------------------------------------------
// Merged RoPE, vectorized 8 lanes/thread (uint4 of both halves).
// Heads 0..15 = q (scaled); heads 16..19 = k.
// ---------------------------------------------------------------------------
__global__ void rope_qk8(const __half* __restrict__ qkvh, const float* __restrict__ cosT,
                         const float* __restrict__ sinT,
                         __half* __restrict__ qh, __half* __restrict__ kh) {
    int idx = blockIdx.x * blockDim.x + threadIdx.x;
    int total = BT * 20 * 8;                  // 8 lanes of 8 elems per head-half
    if (idx >= total) return;
    int pb  = (idx & 7) << 3;                 // p base: 0,8,...,56
    int h   = (idx >> 3) % 20;
    int row = idx / (20 << 3);
    int tp  = row & (TT - 1);

    const __half* base = qkvh + (size_t)row * QKVN + h * HD;
    uint4 v1 = *reinterpret_cast<const uint4*>(base + pb);        // x1[0..7]
    uint4 v2 = *reinterpret_cast<const uint4*>(base + pb + 64);   // x2[0..7]
    const __half2* h1 = reinterpret_cast<const __half2*>(&v1);
    const __half2* h2 = reinterpret_cast<const __half2*>(&v2);
    const float* cp = cosT + tp * HD + pb;
    const float* sp = sinT + tp * HD + pb;

    float scale = (h < NH) ? 0.08838834764831845f : 1.0f;
    uint4 o1, o2;
    uint32_t* po1 = reinterpret_cast<uint32_t*>(&o1);
    uint32_t* po2 = reinterpret_cast<uint32_t*>(&o2);
#pragma unroll
    for (int i = 0; i < 4; i++) {
        float a0 = __half2float(h1[i].x), a1 = __half2float(h1[i].y);
        float b0 = __half2float(h2[i].x), b1 = __half2float(h2[i].y);
        float c0 = cp[2*i], c1 = cp[2*i+1];
        float s0 = sp[2*i], s1 = sp[2*i+1];
        po1[i] = pack2h((a0*c0 - b0*s0) * scale, (a1*c1 - b1*s1) * scale);
        po2[i] = pack2h((b0*c0 + a0*s0) * scale, (b1*c1 + a1*s1) * scale);
    }
    if (h < NH) {
        size_t o = (size_t)row * QD + h * HD + pb;
        *reinterpret_cast<uint4*>(qh + o)      = o1;
        *reinterpret_cast<uint4*>(qh + o + 64) = o2;
    } else {
        size_t o = (size_t)row * KVD + (h - NH) * HD + pb;
        *reinterpret_cast<uint4*>(kh + o)      = o1;
        *reinterpret_cast<uint4*>(kh + o + 64) = o2;
    }
}

// ---------------------------------------------------------------------------
// fp16 mma.sync GEMM: C[M,N] = A[M,K] @ B[N,K]^T (fp32 acc; fp16 or fp32 out)
// CTA 128x256, 8 warps (2m x 4n) of 64x64, K-chunk 64, 2-stage cp.async.
// (Validated inner loop — unchanged.)
// ---------------------------------------------------------------------------
#define KSTRB     144
#define A_BYTES   (128*KSTRB)            // 18432
#define B_BYTES   (256*KSTRB)            // 36864
#define STAGE_B   (A_BYTES + B_BYTES)    // 55296
#define GEMM_SMEM (2*STAGE_B)            // 110592

__device__ __forceinline__ void load_chunk(
    uint32_t st,
    const __half* __restrict__ Ah, const __half* __restrict__ Bh,
    int m0, int n0, int K, int c, int tid)
{
    const size_t ka = (size_t)c * 64;
#pragma unroll
    for (int i = 0; i < 4; i++) {
        int idx = tid + (i << 8);
        int r = idx >> 3, u = idx & 7;
        uint32_t off = (uint32_t)r * KSTRB + ((uint32_t)u << 4);
        cp16(st + off, Ah + (size_t)(m0 + r) * K + ka + ((size_t)u << 3));
    }
#pragma unroll
    for (int i = 0; i < 8; i++) {
        int idx = tid + (i << 8);
        int r = idx >> 3, u = idx & 7;
        uint32_t off = (uint32_t)r * KSTRB + ((uint32_t)u << 4);
        cp16(st + A_BYTES + off, Bh + (size_t)(n0 + r) * K + ka + ((size_t)u << 3));
    }
    asm volatile("cp.async.commit_group;" ::: "memory");
}

template <bool HALF_OUT>
__global__ __launch_bounds__(256, 1)
void gemm_f16(const __half* __restrict__ Ah, const __half* __restrict__ Bh,
              void* __restrict__ Cv, int M, int N, int K)
{
    extern __shared__ __align__(128) char smem[];
    uint32_t sb = s2u(smem);
    const int tid  = threadIdx.x;
    const int lane = tid & 31;
    const int wid  = tid >> 5;
    const int warp_m = wid >> 2;
    const int warp_n = wid & 3;
    const int m0 = blockIdx.y << 7;
    const int n0 = blockIdx.x << 8;
    const int nch = K >> 6;

    load_chunk(sb,           Ah, Bh, m0, n0, K, 0, tid);
    load_chunk(sb + STAGE_B, Ah, Bh, m0, n0, K, 1, tid);

    const uint32_t a_off = (uint32_t)(warp_m * 64 + (lane & 15)) * KSTRB
                         + ((uint32_t)(lane >> 4) << 4);
    const uint32_t b_off = (uint32_t)(warp_n * 64 + (lane & 7) + ((lane >> 4) << 3)) * KSTRB
                         + ((uint32_t)((lane >> 3) & 1) << 4);

    float acc[4][8][4];
#pragma unroll
    for (int m = 0; m < 4; m++)
#pragma unroll
        for (int n = 0; n < 8; n++)
#pragma unroll
            for (int j = 0; j < 4; j++) acc[m][n][j] = 0.0f;

    for (int c = 0; c < nch; c++) {
        const uint32_t st = sb + (uint32_t)(c & 1) * STAGE_B;
        if (c == nch - 1) asm volatile("cp.async.wait_group 0;" ::: "memory");
        else              asm volatile("cp.async.wait_group 1;" ::: "memory");
        __syncthreads();

        const uint32_t sAh = st;
        const uint32_t sBh = st + A_BYTES;

#pragma unroll
        for (int ks = 0; ks < 4; ks++) {
            const uint32_t ak = a_off + (uint32_t)ks * 32;
            const uint32_t bk = b_off + (uint32_t)ks * 32;
            uint32_t ah[4][4], bh[4][4];
#pragma unroll
            for (int m = 0; m < 4; m++)
                ldsm4(ah[m], sAh + ak + m*16*KSTRB);
#pragma unroll
            for (int p = 0; p < 4; p++)
                ldsm4(bh[p], sBh + bk + p*16*KSTRB);
#pragma unroll
            for (int m = 0; m < 4; m++)
#pragma unroll
                for (int n = 0; n < 8; n++) {
                    const int p = n >> 1, q = (n & 1) << 1;
                    mma16816(acc[m][n], ah[m], bh[p][q], bh[p][q+1]);
                }
        }
        __syncthreads();
        if (c + 2 < nch)
            load_chunk(st, Ah, Bh, m0, n0, K, c + 2, tid);
    }

    const int row0 = m0 + warp_m * 64 + (lane >> 2);
    const int col0 = n0 + warp_n * 64 + ((lane & 3) << 1);
    if (HALF_OUT) {
        __half* C = (__half*)Cv;
#pragma unroll
        for (int m = 0; m < 4; m++) {
#pragma unroll
            for (int n = 0; n < 8; n++) {
                size_t o0 = (size_t)(row0 + m*16)     * N + col0 + n*8;
                size_t o1 = (size_t)(row0 + m*16 + 8) * N + col0 + n*8;
                *reinterpret_cast<uint32_t*>(&C[o0]) = pack2h(acc[m][n][0], acc[m][n][1]);
                *reinterpret_cast<uint32_t*>(&C[o1]) = pack2h(acc[m][n][2], acc[m][n][3]);
            }
        }
    } else {
        float* C = (float*)Cv;
#pragma unroll
        for (int m = 0; m < 4; m++) {
#pragma unroll
            for (int n = 0; n < 8; n++) {
                float* p0 = C + (size_t)(row0 + m*16)     * N + col0 + n*8;
                float* p1 = C + (size_t)(row0 + m*16 + 8) * N + col0 + n*8;
                *(float2*)p0 = make_float2(acc[m][n][0], acc[m][n][1]);
                *(float2*)p1 = make_float2(acc[m][n][2], acc[m][n][3]);
            }
        }
    }
}

// ---------------------------------------------------------------------------
// Tensor-core causal GQA flash attention (single-fp16 Q/K/V/P, max-free
// softmax, fp32 accumulators). Inner loop unchanged; occupancy 2 CTAs/SM.
// ---------------------------------------------------------------------------
#define QSTR 272
#define KSTR 272
#define VSTR 144
#define Q_BYTES   (128*QSTR)
#define K_BYTES   (64*KSTR)
#define V_BYTES   (128*VSTR)
#define KV_STAGE  (K_BYTES + V_BYTES)
#define ATTN_SMEM (Q_BYTES + 2*KV_STAGE)  // 106496 (x2 = 212992 <= 228KB/SM)

__device__ __forceinline__ void attn_load_kv(uint32_t base, int b, int kvh,
                                             int kt, int tid) {
    const int kr0 = kt << 6;
#pragma unroll
    for (int i = 0; i < 4; i++) {
        int idx = tid + (i << 8);
        int r = idx >> 4, u = idx & 15;
        uint32_t off = (uint32_t)r * KSTR + ((uint32_t)u << 4);
        size_t g = ((size_t)(b * TT + kr0 + r)) * KVD + kvh * HD + ((size_t)u << 3);
        cp16(base + off, g_kh + g);
    }
#pragma unroll
    for (int i = 0; i < 4; i++) {
        int idx = tid + (i << 8);
        int d = idx >> 3, u = idx & 7;
        uint32_t off = (uint32_t)d * VSTR + ((uint32_t)u << 4);
        size_t g = ((size_t)b * KVD + kvh * HD + d) * TT + kr0 + ((size_t)u << 3);
        cp16(base + K_BYTES + off, g_vth + g);
    }
    asm volatile("cp.async.commit_group;" ::: "memory");
}

__global__ __launch_bounds__(256, 2) void attn_mma() {
    extern __shared__ __align__(128) char smem[];
    uint32_t sb = s2u(smem);
    const uint32_t sQh = sb;
    const uint32_t sKV = sb + Q_BYTES;

    const int tid = threadIdx.x, lane = tid & 31, w = tid >> 5;
    const int qb = (gridDim.x - 1) - blockIdx.x;
    const int hy = blockIdx.y, b = blockIdx.z;
    const int kvh = hy >> 2;
    const int qbase = qb << 7;
    const int nkt = 2 * qb + 2;

#pragma unroll
    for (int i = 0; i < 8; i++) {
        int idx = tid + (i << 8);
        int r = idx >> 4, u = idx & 15;
        uint32_t off = (uint32_t)r * QSTR + ((uint32_t)u << 4);
        size_t g = ((size_t)(b * TT + qbase + r)) * QD + hy * HD + ((size_t)u << 3);
        cp16(sQh + off, g_qh + g);
    }
    attn_load_kv(sKV, b, kvh, 0, tid);
    attn_load_kv(sKV + KV_STAGE, b, kvh, 1, tid);

    const uint32_t a_off = (uint32_t)(w * 16 + (lane & 15)) * QSTR
                         + ((uint32_t)(lane >> 4) << 4);
    const uint32_t kb_off = (uint32_t)((lane & 7) + ((lane >> 4) << 3)) * KSTR
                          + ((uint32_t)((lane >> 3) & 1) << 4);
    const uint32_t vb_off = (uint32_t)((lane & 7) + ((lane >> 4) << 3)) * VSTR
                          + ((uint32_t)((lane >> 3) & 1) << 4);

    float o[16][4];
#pragma unroll
    for (int n = 0; n < 16; n++)
#pragma unroll
        for (int j = 0; j < 4; j++) o[n][j] = 0.0f;
    float rs0 = 0.0f, rs1 = 0.0f;

    const int qr = qbase + w * 16 + (lane >> 2);

    for (int kt = 0; kt < nkt; kt++) {
        const uint32_t stb = sKV + (uint32_t)(kt & 1) * KV_STAGE;
        if (kt < nkt - 1) asm volatile("cp.async.wait_group 1;" ::: "memory");
        else              asm volatile("cp.async.wait_group 0;" ::: "memory");
        __syncthreads();

        float sc[8][4];
#pragma unroll
        for (int n = 0; n < 8; n++)
#pragma unroll
            for (int j = 0; j < 4; j++) sc[n][j] = 0.0f;

#pragma unroll
        for (int ks = 0; ks < 8; ks++) {
            uint32_t ah[4];
            ldsm4(ah, sQh + a_off + ks*32);
#pragma unroll
            for (int p = 0; p < 4; p++) {
                uint32_t kh[4];
                uint32_t ka = kb_off + (uint32_t)p * 16 * KSTR + (uint32_t)ks * 32;
                ldsm4(kh, stb + ka);
                mma16816(sc[2*p],   ah, kh[0], kh[1]);
                mma16816(sc[2*p+1], ah, kh[2], kh[3]);
            }
        }

        const int kc0 = kt << 6;
        if (kc0 + 63 > qbase + w * 16) {
#pragma unroll
            for (int j = 0; j < 8; j++) {
                int col = kc0 + j*8 + ((lane & 3) << 1);
                if (col     > qr)     sc[j][0] = -1e30f;
                if (col + 1 > qr)     sc[j][1] = -1e30f;
                if (col     > qr + 8) sc[j][2] = -1e30f;
                if (col + 1 > qr + 8) sc[j][3] = -1e30f;
            }
        }

#pragma unroll
        for (int j = 0; j < 8; j++) {
            sc[j][0] = __expf(sc[j][0]);
            sc[j][1] = __expf(sc[j][1]);
            sc[j][2] = __expf(sc[j][2]);
            sc[j][3] = __expf(sc[j][3]);
            rs0 += sc[j][0] + sc[j][1];
            rs1 += sc[j][2] + sc[j][3];
        }

#pragma unroll
        for (int ks = 0; ks < 4; ks++) {
            uint32_t pah[4];
            pah[0] = pack2h(sc[2*ks][0],   sc[2*ks][1]);
            pah[1] = pack2h(sc[2*ks][2],   sc[2*ks][3]);
            pah[2] = pack2h(sc[2*ks+1][0], sc[2*ks+1][1]);
            pah[3] = pack2h(sc[2*ks+1][2], sc[2*ks+1][3]);
#pragma unroll
            for (int p = 0; p < 8; p++) {
                uint32_t vh[4];
                uint32_t va = vb_off + (uint32_t)p * 16 * VSTR + (uint32_t)ks * 32;
                ldsm4(vh, stb + K_BYTES + va);
                mma16816(o[2*p],   pah, vh[0], vh[1]);
                mma16816(o[2*p+1], pah, vh[2], vh[3]);
            }
        }
        __syncthreads();
        if (kt + 2 < nkt)
            attn_load_kv(stb, b, kvh, kt + 2, tid);
    }

    rs0 += __shfl_xor_sync(0xffffffffu, rs0, 1);
    rs0 += __shfl_xor_sync(0xffffffffu, rs0, 2);
    rs1 += __shfl_xor_sync(0xffffffffu, rs1, 1);
    rs1 += __shfl_xor_sync(0xffffffffu, rs1, 2);
    const float inv0 = 1.0f / rs0, inv1 = 1.0f / rs1;
    const int row0 = qbase + w * 16 + (lane >> 2);
#pragma unroll
    for (int n = 0; n < 16; n++) {
        int dcol = n * 8 + ((lane & 3) << 1);
        size_t g0 = ((size_t)(b * TT + row0))     * QD + hy * HD + dcol;
        size_t g1 = ((size_t)(b * TT + row0 + 8)) * QD + hy * HD + dcol;
        *reinterpret_cast<uint32_t*>(&g_ah[g0]) = pack2h(o[n][0] * inv0, o[n][1] * inv0);
        *reinterpret_cast<uint32_t*>(&g_ah[g1]) = pack2h(o[n][2] * inv1, o[n][3] * inv1);
    }
}

// ---------------------------------------------------------------------------
// Launch
// ---------------------------------------------------------------------------
extern "C" void kernel_launch(void* const* d_in, const int* in_sizes, int n_in,
                              void* d_out, int out_size) {
    const float* x  = (const float*)d_in[0];
    const float* rc = (const float*)d_in[1];
    const float* rs = (const float*)d_in[2];
    const float* Wq = (const float*)d_in[3];
    const float* Wk = (const float*)d_in[4];
    const float* Wv = (const float*)d_in[5];
    const float* Wo = (const float*)d_in[6];
    float* out = (float*)d_out;

    __half *qkvh, *xh, *ah, *qh, *kh, *vth, *wh, *woh;
    cudaGetSymbolAddress((void**)&qkvh, g_qkvh);
    cudaGetSymbolAddress((void**)&xh,   g_xh);
    cudaGetSymbolAddress((void**)&ah,   g_ah);
    cudaGetSymbolAddress((void**)&qh,   g_qh);
    cudaGetSymbolAddress((void**)&kh,   g_kh);
    cudaGetSymbolAddress((void**)&vth,  g_vth);
    cudaGetSymbolAddress((void**)&wh,   g_wh);
    cudaGetSymbolAddress((void**)&woh,  g_woh);

    cudaFuncSetAttribute(gemm_f16<true>,  cudaFuncAttributeMaxDynamicSharedMemorySize, GEMM_SMEM);
    cudaFuncSetAttribute(gemm_f16<false>, cudaFuncAttributeMaxDynamicSharedMemorySize, GEMM_SMEM);
    cudaFuncSetAttribute(attn_mma,        cudaFuncAttributeMaxDynamicSharedMemorySize, ATTN_SMEM);

    // Convert x; merged weight transpose (one launch for all 4 matrices)
    cvt_kernel4<<<(BT*HIDN/4 + 255)/256, 256>>>((const float4*)x, (uint2*)xh, BT*HIDN/4);
    wtrans4<<<dim3(64, 64, 4), dim3(32, 8)>>>(Wq, Wk, Wv, Wo, wh, woh);

    // Fused Q|K|V projection (N=3072, fp16 output)
    gemm_f16<true><<<dim3(QKVN/256, BT/128), 256, GEMM_SMEM>>>(xh, wh, qkvh, BT, QKVN, HIDN);

    // Merged vectorized RoPE (q+k); V transpose
    rope_qk8<<<(BT * 20 * 8 + 255) / 256, 256>>>(qkvh, rc, rs, qh, kh);
    vtrans_h<<<dim3(TT/32, KVD/32, BB), dim3(32, 8)>>>(qkvh, vth);

    // Tensor-core causal GQA flash attention (writes g_ah fp16)
    attn_mma<<<dim3(TT/128, NH, BB), 256, ATTN_SMEM>>>();

    // Output projection (fp32 output to d_out)
    gemm_f16<false><<<dim3(HIDN/256, BT/128), 256, GEMM_SMEM>>>(ah, woh, out, BT, HIDN, QD);
}

// round 15
// speedup vs baseline: 1.0220x; 1.0220x over previous
#include <cuda_runtime.h>
#include <cuda_fp16.h>
#include <cstdint>

// Problem constants
#define BB   2
#define TT   2048
#define HIDN 2048
#define NH   16
#define NKV  4
#define HD   128
#define BT   (BB*TT)          // 4096
#define QD   (NH*HD)          // 2048
#define KVD  (NKV*HD)         // 512
#define QKVN (QD + 2*KVD)     // 3072 (fused Q|K|V projection width)

// ---------------------------------------------------------------------------
// Scratch (allocation-free rule: __device__ globals). All-fp16 intermediates.
// ---------------------------------------------------------------------------
__device__ __half g_qkvh[(size_t)BT*QKVN];          // fp16 QKV gemm output
__device__ __half g_xh [(size_t)BT*HIDN];           // x: fp16
__device__ __half g_ah [(size_t)BT*QD];             // attention out: fp16
__device__ __half g_qh [(size_t)BT*QD];             // Q: fp16 (pre-scaled, roped)
__device__ __half g_kh [(size_t)BT*KVD];            // K: fp16 (roped)
__device__ __half g_vth[(size_t)BT*KVD];            // Vt: fp16, [b*KVD + ch][t]
__device__ __half g_wh [(size_t)QKVN*HIDN];         // rows: Wq^T | Wk^T | Wv^T
__device__ __half g_woh[(size_t)HIDN*QD];           // Wo^T

// ---------------------------------------------------------------------------
// PTX helpers (baseline PTX only — harness targets compute_103, no tcgen05)
// ---------------------------------------------------------------------------
__device__ __forceinline__ uint32_t s2u(const void* p) {
    return (uint32_t)__cvta_generic_to_shared(p);
}
__device__ __forceinline__ void cp16(uint32_t s, const void* g) {
    asm volatile("cp.async.cg.shared.global [%0], [%1], 16;" :: "r"(s), "l"(g));
}
__device__ __forceinline__ void ldsm4(uint32_t* r, uint32_t addr) {
    asm volatile("ldmatrix.sync.aligned.m8n8.x4.shared.b16 {%0,%1,%2,%3}, [%4];"
                 : "=r"(r[0]), "=r"(r[1]), "=r"(r[2]), "=r"(r[3]) : "r"(addr));
}
__device__ __forceinline__ void mma16816(float* d,
                                         const uint32_t* a, uint32_t b0, uint32_t b1) {
    asm volatile("mma.sync.aligned.m16n8k16.row.col.f32.f16.f16.f32 "
                 "{%0,%1,%2,%3}, {%4,%5,%6,%7}, {%8,%9}, {%0,%1,%2,%3};"
                 : "+f"(d[0]), "+f"(d[1]), "+f"(d[2]), "+f"(d[3])
                 : "r"(a[0]), "r"(a[1]), "r"(a[2]), "r"(a[3]), "r"(b0), "r"(b1));
}
__device__ __forceinline__ uint32_t pack2h(float v0, float v1) {
    __half2 h = __floats2half2_rn(v0, v1);
    return *reinterpret_cast<uint32_t*>(&h);
}

// ---------------------------------------------------------------------------
// Convert fp32 -> fp16, vectorized 4 elems/thread
// ---------------------------------------------------------------------------
__global__ void cvt_kernel4(const float4* __restrict__ in,
                            uint2* __restrict__ hi, int n4) {
    int i = blockIdx.x * blockDim.x + threadIdx.x;
    if (i >= n4) return;
    float4 v = in[i];
    uint2 h;
    h.x = pack2h(v.x, v.y);
    h.y = pack2h(v.z, v.w);
    hi[i] = h;
}

// ---------------------------------------------------------------------------
// Merged weight transpose: 4 matrices (Wq, Wk, Wv, Wo), all 2048 input rows.
// z selects matrix. in [2048][Ncols] fp32 -> out [Ncols][2048] fp16.
// Stores vectorized as half2.
// ---------------------------------------------------------------------------
__global__ void wtrans4(const float* __restrict__ Wq, const float* __restrict__ Wk,
                        const float* __restrict__ Wv, const float* __restrict__ Wo,
                        __half* __restrict__ wh, __half* __restrict__ woh) {
    const float* in;
    __half* out;
    int Ncols;
    switch (blockIdx.z) {
        case 0:  in = Wq; out = wh;                           Ncols = QD;   break;
        case 1:  in = Wk; out = wh + (size_t)QD*HIDN;         Ncols = KVD;  break;
        case 2:  in = Wv; out = wh + (size_t)(QD+KVD)*HIDN;   Ncols = KVD;  break;
        default: in = Wo; out = woh;                          Ncols = HIDN; break;
    }
    int c0 = blockIdx.x * 32;
    if (c0 >= Ncols) return;
    int r0 = blockIdx.y * 32;
    __shared__ float t[32][33];
    int tx = threadIdx.x, ty = threadIdx.y;
    for (int i = ty; i < 32; i += 8)
        t[i][tx] = in[(size_t)(r0 + i) * Ncols + c0 + tx];
    __syncthreads();
    int tr = (tx & 15) * 2;              // output-row pair within tile
    int jc = ty + ((tx >> 4) << 3);      // output column 0..15
    for (int rep = 0; rep < 2; rep++, jc += 16) {
        __half2 v = __floats2half2_rn(t[tr][jc], t[tr + 1][jc]);
        *reinterpret_cast<__half2*>(&out[(size_t)(c0 + jc) * HIDN + r0 + tr]) = v;
    }
}

// ---------------------------------------------------------------------------
// V transpose: g_qkvh [b*TT + t][QKVN] (v at col 2560+) -> vt [b*KVD + ch][TT]
// ---------------------------------------------------------------------------
__global__ void vtrans_h(const __half* __restrict__ v,
                         __half* __restrict__ hi) {
    __shared__ float t[32][33];
    int t0 = blockIdx.x * 32, c0 = blockIdx.y * 32, b = blockIdx.z;
    int tx = threadIdx.x, ty = threadIdx.y;
    for (int i = ty; i < 32; i += 8)
        t[i][tx] = __half2float(v[((size_t)(b * TT + t0 + i)) * QKVN + QD + KVD + c0 + tx]);
    __syncthreads();
    for (int j = ty; j < 32; j += 8)
        hi[((size_t)b * KVD + c0 + j) * TT + t0 + tx] = __float2half(t[tx][j]);
}

// ---------------------------------------------------------------------------
// Merged RoPE, vectorized 8 lanes/thread (uint4 of both halves).
// Heads 0..15 = q (scaled); heads 16..19 = k.
// ---------------------------------------------------------------------------
__global__ void rope_qk8(const __half* __restrict__ qkvh, const float* __restrict__ cosT,
                         const float* __restrict__ sinT,
                         __half* __restrict__ qh, __half* __restrict__ kh) {
    int idx = blockIdx.x * blockDim.x + threadIdx.x;
    int total = BT * 20 * 8;
    if (idx >= total) return;
    int pb  = (idx & 7) << 3;
    int h   = (idx >> 3) % 20;
    int row = idx / (20 << 3);
    int tp  = row & (TT - 1);

    const __half* base = qkvh + (size_t)row * QKVN + h * HD;
    uint4 v1 = *reinterpret_cast<const uint4*>(base + pb);
    uint4 v2 = *reinterpret_cast<const uint4*>(base + pb + 64);
    const __half2* h1 = reinterpret_cast<const __half2*>(&v1);
    const __half2* h2 = reinterpret_cast<const __half2*>(&v2);
    const float* cp = cosT + tp * HD + pb;
    const float* sp = sinT + tp * HD + pb;

    float scale = (h < NH) ? 0.08838834764831845f : 1.0f;
    uint4 o1, o2;
    uint32_t* po1 = reinterpret_cast<uint32_t*>(&o1);
    uint32_t* po2 = reinterpret_cast<uint32_t*>(&o2);
#pragma unroll
    for (int i = 0; i < 4; i++) {
        float a0 = __half2float(h1[i].x), a1 = __half2float(h1[i].y);
        float b0 = __half2float(h2[i].x), b1 = __half2float(h2[i].y);
        float c0 = cp[2*i], c1 = cp[2*i+1];
        float s0 = sp[2*i], s1 = sp[2*i+1];
        po1[i] = pack2h((a0*c0 - b0*s0) * scale, (a1*c1 - b1*s1) * scale);
        po2[i] = pack2h((b0*c0 + a0*s0) * scale, (b1*c1 + a1*s1) * scale);
    }
    if (h < NH) {
        size_t o = (size_t)row * QD + h * HD + pb;
        *reinterpret_cast<uint4*>(qh + o)      = o1;
        *reinterpret_cast<uint4*>(qh + o + 64) = o2;
    } else {
        size_t o = (size_t)row * KVD + (h - NH) * HD + pb;
        *reinterpret_cast<uint4*>(kh + o)      = o1;
        *reinterpret_cast<uint4*>(kh + o + 64) = o2;
    }
}

// ---------------------------------------------------------------------------
// fp16 mma.sync GEMM: C[M,N] = A[M,K] @ B[N,K]^T (fp32 acc; fp16 or fp32 out)
// CTA 128x256, 8 warps (2m x 4n) of 64x64, K-chunk 64, 2-stage cp.async.
// (Validated inner loop — unchanged.)
// ---------------------------------------------------------------------------
#define KSTRB     144
#define A_BYTES   (128*KSTRB)            // 18432
#define B_BYTES   (256*KSTRB)            // 36864
#define STAGE_B   (A_BYTES + B_BYTES)    // 55296
#define GEMM_SMEM (2*STAGE_B)            // 110592

__device__ __forceinline__ void load_chunk(
    uint32_t st,
    const __half* __restrict__ Ah, const __half* __restrict__ Bh,
    int m0, int n0, int K, int c, int tid)
{
    const size_t ka = (size_t)c * 64;
#pragma unroll
    for (int i = 0; i < 4; i++) {
        int idx = tid + (i << 8);
        int r = idx >> 3, u = idx & 7;
        uint32_t off = (uint32_t)r * KSTRB + ((uint32_t)u << 4);
        cp16(st + off, Ah + (size_t)(m0 + r) * K + ka + ((size_t)u << 3));
    }
#pragma unroll
    for (int i = 0; i < 8; i++) {
        int idx = tid + (i << 8);
        int r = idx >> 3, u = idx & 7;
        uint32_t off = (uint32_t)r * KSTRB + ((uint32_t)u << 4);
        cp16(st + A_BYTES + off, Bh + (size_t)(n0 + r) * K + ka + ((size_t)u << 3));
    }
    asm volatile("cp.async.commit_group;" ::: "memory");
}

template <bool HALF_OUT>
__global__ __launch_bounds__(256, 1)
void gemm_f16(const __half* __restrict__ Ah, const __half* __restrict__ Bh,
              void* __restrict__ Cv, int M, int N, int K)
{
    extern __shared__ __align__(128) char smem[];
    uint32_t sb = s2u(smem);
    const int tid  = threadIdx.x;
    const int lane = tid & 31;
    const int wid  = tid >> 5;
    const int warp_m = wid >> 2;
    const int warp_n = wid & 3;
    const int m0 = blockIdx.y << 7;
    const int n0 = blockIdx.x << 8;
    const int nch = K >> 6;

    load_chunk(sb,           Ah, Bh, m0, n0, K, 0, tid);
    load_chunk(sb + STAGE_B, Ah, Bh, m0, n0, K, 1, tid);

    const uint32_t a_off = (uint32_t)(warp_m * 64 + (lane & 15)) * KSTRB
                         + ((uint32_t)(lane >> 4) << 4);
    const uint32_t b_off = (uint32_t)(warp_n * 64 + (lane & 7) + ((lane >> 4) << 3)) * KSTRB
                         + ((uint32_t)((lane >> 3) & 1) << 4);

    float acc[4][8][4];
#pragma unroll
    for (int m = 0; m < 4; m++)
#pragma unroll
        for (int n = 0; n < 8; n++)
#pragma unroll
            for (int j = 0; j < 4; j++) acc[m][n][j] = 0.0f;

    for (int c = 0; c < nch; c++) {
        const uint32_t st = sb + (uint32_t)(c & 1) * STAGE_B;
        if (c == nch - 1) asm volatile("cp.async.wait_group 0;" ::: "memory");
        else              asm volatile("cp.async.wait_group 1;" ::: "memory");
        __syncthreads();

        const uint32_t sAh = st;
        const uint32_t sBh = st + A_BYTES;

#pragma unroll
        for (int ks = 0; ks < 4; ks++) {
            const uint32_t ak = a_off + (uint32_t)ks * 32;
            const uint32_t bk = b_off + (uint32_t)ks * 32;
            uint32_t ah[4][4], bh[4][4];
#pragma unroll
            for (int m = 0; m < 4; m++)
                ldsm4(ah[m], sAh + ak + m*16*KSTRB);
#pragma unroll
            for (int p = 0; p < 4; p++)
                ldsm4(bh[p], sBh + bk + p*16*KSTRB);
#pragma unroll
            for (int m = 0; m < 4; m++)
#pragma unroll
                for (int n = 0; n < 8; n++) {
                    const int p = n >> 1, q = (n & 1) << 1;
                    mma16816(acc[m][n], ah[m], bh[p][q], bh[p][q+1]);
                }
        }
        __syncthreads();
        if (c + 2 < nch)
            load_chunk(st, Ah, Bh, m0, n0, K, c + 2, tid);
    }

    const int row0 = m0 + warp_m * 64 + (lane >> 2);
    const int col0 = n0 + warp_n * 64 + ((lane & 3) << 1);
    if (HALF_OUT) {
        __half* C = (__half*)Cv;
#pragma unroll
        for (int m = 0; m < 4; m++) {
#pragma unroll
            for (int n = 0; n < 8; n++) {
                size_t o0 = (size_t)(row0 + m*16)     * N + col0 + n*8;
                size_t o1 = (size_t)(row0 + m*16 + 8) * N + col0 + n*8;
                *reinterpret_cast<uint32_t*>(&C[o0]) = pack2h(acc[m][n][0], acc[m][n][1]);
                *reinterpret_cast<uint32_t*>(&C[o1]) = pack2h(acc[m][n][2], acc[m][n][3]);
            }
        }
    } else {
        float* C = (float*)Cv;
#pragma unroll
        for (int m = 0; m < 4; m++) {
#pragma unroll
            for (int n = 0; n < 8; n++) {
                float* p0 = C + (size_t)(row0 + m*16)     * N + col0 + n*8;
                float* p1 = C + (size_t)(row0 + m*16 + 8) * N + col0 + n*8;
                *(float2*)p0 = make_float2(acc[m][n][0], acc[m][n][1]);
                *(float2*)p1 = make_float2(acc[m][n][2], acc[m][n][3]);
            }
        }
    }
}

// ---------------------------------------------------------------------------
// Tensor-core causal GQA flash attention (single-fp16 Q/K/V/P, max-free
// softmax, fp32 accumulators). Occupancy 1 (R13-validated; occ-2 spilled).
// ---------------------------------------------------------------------------
#define QSTR 272
#define KSTR 272
#define VSTR 144
#define Q_BYTES   (128*QSTR)
#define K_BYTES   (64*KSTR)
#define V_BYTES   (128*VSTR)
#define KV_STAGE  (K_BYTES + V_BYTES)
#define ATTN_SMEM (Q_BYTES + 2*KV_STAGE)  // 106496

__device__ __forceinline__ void attn_load_kv(uint32_t base, int b, int kvh,
                                             int kt, int tid) {
    const int kr0 = kt << 6;
#pragma unroll
    for (int i = 0; i < 4; i++) {
        int idx = tid + (i << 8);
        int r = idx >> 4, u = idx & 15;
        uint32_t off = (uint32_t)r * KSTR + ((uint32_t)u << 4);
        size_t g = ((size_t)(b * TT + kr0 + r)) * KVD + kvh * HD + ((size_t)u << 3);
        cp16(base + off, g_kh + g);
    }
#pragma unroll
    for (int i = 0; i < 4; i++) {
        int idx = tid + (i << 8);
        int d = idx >> 3, u = idx & 7;
        uint32_t off = (uint32_t)d * VSTR + ((uint32_t)u << 4);
        size_t g = ((size_t)b * KVD + kvh * HD + d) * TT + kr0 + ((size_t)u << 3);
        cp16(base + K_BYTES + off, g_vth + g);
    }
    asm volatile("cp.async.commit_group;" ::: "memory");
}

__global__ __launch_bounds__(256, 1) void attn_mma() {
    extern __shared__ __align__(128) char smem[];
    uint32_t sb = s2u(smem);
    const uint32_t sQh = sb;
    const uint32_t sKV = sb + Q_BYTES;

    const int tid = threadIdx.x, lane = tid & 31, w = tid >> 5;
    const int qb = (gridDim.x - 1) - blockIdx.x;
    const int hy = blockIdx.y, b = blockIdx.z;
    const int kvh = hy >> 2;
    const int qbase = qb << 7;
    const int nkt = 2 * qb + 2;

#pragma unroll
    for (int i = 0; i < 8; i++) {
        int idx = tid + (i << 8);
        int r = idx >> 4, u = idx & 15;
        uint32_t off = (uint32_t)r * QSTR + ((uint32_t)u << 4);
        size_t g = ((size_t)(b * TT + qbase + r)) * QD + hy * HD + ((size_t)u << 3);
        cp16(sQh + off, g_qh + g);
    }
    attn_load_kv(sKV, b, kvh, 0, tid);
    attn_load_kv(sKV + KV_STAGE, b, kvh, 1, tid);

    const uint32_t a_off = (uint32_t)(w * 16 + (lane & 15)) * QSTR
                         + ((uint32_t)(lane >> 4) << 4);
    const uint32_t kb_off = (uint32_t)((lane & 7) + ((lane >> 4) << 3)) * KSTR
                          + ((uint32_t)((lane >> 3) & 1) << 4);
    const uint32_t vb_off = (uint32_t)((lane & 7) + ((lane >> 4) << 3)) * VSTR
                          + ((uint32_t)((lane >> 3) & 1) << 4);

    float o[16][4];
#pragma unroll
    for (int n = 0; n < 16; n++)
#pragma unroll
        for (int j = 0; j < 4; j++) o[n][j] = 0.0f;
    float rs0 = 0.0f, rs1 = 0.0f;

    const int qr = qbase + w * 16 + (lane >> 2);

    for (int kt = 0; kt < nkt; kt++) {
        const uint32_t stb = sKV + (uint32_t)(kt & 1) * KV_STAGE;
        if (kt < nkt - 1) asm volatile("cp.async.wait_group 1;" ::: "memory");
        else              asm volatile("cp.async.wait_group 0;" ::: "memory");
        __syncthreads();

        float sc[8][4];
#pragma unroll
        for (int n = 0; n < 8; n++)
#pragma unroll
            for (int j = 0; j < 4; j++) sc[n][j] = 0.0f;

#pragma unroll
        for (int ks = 0; ks < 8; ks++) {
            uint32_t ah[4];
            ldsm4(ah, sQh + a_off + ks*32);
#pragma unroll
            for (int p = 0; p < 4; p++) {
                uint32_t kh[4];
                uint32_t ka = kb_off + (uint32_t)p * 16 * KSTR + (uint32_t)ks * 32;
                ldsm4(kh, stb + ka);
                mma16816(sc[2*p],   ah, kh[0], kh[1]);
                mma16816(sc[2*p+1], ah, kh[2], kh[3]);
            }
        }

        const int kc0 = kt << 6;
        if (kc0 + 63 > qbase + w * 16) {
#pragma unroll
            for (int j = 0; j < 8; j++) {
                int col = kc0 + j*8 + ((lane & 3) << 1);
                if (col     > qr)     sc[j][0] = -1e30f;
                if (col + 1 > qr)     sc[j][1] = -1e30f;
                if (col     > qr + 8) sc[j][2] = -1e30f;
                if (col + 1 > qr + 8) sc[j][3] = -1e30f;
            }
        }

#pragma unroll
        for (int j = 0; j < 8; j++) {
            sc[j][0] = __expf(sc[j][0]);
            sc[j][1] = __expf(sc[j][1]);
            sc[j][2] = __expf(sc[j][2]);
            sc[j][3] = __expf(sc[j][3]);
            rs0 += sc[j][0] + sc[j][1];
            rs1 += sc[j][2] + sc[j][3];
        }

#pragma unroll
        for (int ks = 0; ks < 4; ks++) {
            uint32_t pah[4];
            pah[0] = pack2h(sc[2*ks][0],   sc[2*ks][1]);
            pah[1] = pack2h(sc[2*ks][2],   sc[2*ks][3]);
            pah[2] = pack2h(sc[2*ks+1][0], sc[2*ks+1][1]);
            pah[3] = pack2h(sc[2*ks+1][2], sc[2*ks+1][3]);
#pragma unroll
            for (int p = 0; p < 8; p++) {
                uint32_t vh[4];
                uint32_t va = vb_off + (uint32_t)p * 16 * VSTR + (uint32_t)ks * 32;
                ldsm4(vh, stb + K_BYTES + va);
                mma16816(o[2*p],   pah, vh[0], vh[1]);
                mma16816(o[2*p+1], pah, vh[2], vh[3]);
            }
        }
        __syncthreads();
        if (kt + 2 < nkt)
            attn_load_kv(stb, b, kvh, kt + 2, tid);
    }

    rs0 += __shfl_xor_sync(0xffffffffu, rs0, 1);
    rs0 += __shfl_xor_sync(0xffffffffu, rs0, 2);
    rs1 += __shfl_xor_sync(0xffffffffu, rs1, 1);
    rs1 += __shfl_xor_sync(0xffffffffu, rs1, 2);
    const float inv0 = 1.0f / rs0, inv1 = 1.0f / rs1;
    const int row0 = qbase + w * 16 + (lane >> 2);
#pragma unroll
    for (int n = 0; n < 16; n++) {
        int dcol = n * 8 + ((lane & 3) << 1);
        size_t g0 = ((size_t)(b * TT + row0))     * QD + hy * HD + dcol;
        size_t g1 = ((size_t)(b * TT + row0 + 8)) * QD + hy * HD + dcol;
        *reinterpret_cast<uint32_t*>(&g_ah[g0]) = pack2h(o[n][0] * inv0, o[n][1] * inv0);
        *reinterpret_cast<uint32_t*>(&g_ah[g1]) = pack2h(o[n][2] * inv1, o[n][3] * inv1);
    }
}

// ---------------------------------------------------------------------------
// Launch
// ---------------------------------------------------------------------------
extern "C" void kernel_launch(void* const* d_in, const int* in_sizes, int n_in,
                              void* d_out, int out_size) {
    const float* x  = (const float*)d_in[0];
    const float* rc = (const float*)d_in[1];
    const float* rs = (const float*)d_in[2];
    const float* Wq = (const float*)d_in[3];
    const float* Wk = (const float*)d_in[4];
    const float* Wv = (const float*)d_in[5];
    const float* Wo = (const float*)d_in[6];
    float* out = (float*)d_out;

    __half *qkvh, *xh, *ah, *qh, *kh, *vth, *wh, *woh;
    cudaGetSymbolAddress((void**)&qkvh, g_qkvh);
    cudaGetSymbolAddress((void**)&xh,   g_xh);
    cudaGetSymbolAddress((void**)&ah,   g_ah);
    cudaGetSymbolAddress((void**)&qh,   g_qh);
    cudaGetSymbolAddress((void**)&kh,   g_kh);
    cudaGetSymbolAddress((void**)&vth,  g_vth);
    cudaGetSymbolAddress((void**)&wh,   g_wh);
    cudaGetSymbolAddress((void**)&woh,  g_woh);

    cudaFuncSetAttribute(gemm_f16<true>,  cudaFuncAttributeMaxDynamicSharedMemorySize, GEMM_SMEM);
    cudaFuncSetAttribute(gemm_f16<false>, cudaFuncAttributeMaxDynamicSharedMemorySize, GEMM_SMEM);
    cudaFuncSetAttribute(attn_mma,        cudaFuncAttributeMaxDynamicSharedMemorySize, ATTN_SMEM);

    // Convert x; merged weight transpose (one launch for all 4 matrices)
    cvt_kernel4<<<(BT*HIDN/4 + 255)/256, 256>>>((const float4*)x, (uint2*)xh, BT*HIDN/4);
    wtrans4<<<dim3(64, 64, 4), dim3(32, 8)>>>(Wq, Wk, Wv, Wo, wh, woh);

    // Fused Q|K|V projection (N=3072, fp16 output)
    gemm_f16<true><<<dim3(QKVN/256, BT/128), 256, GEMM_SMEM>>>(xh, wh, qkvh, BT, QKVN, HIDN);

    // Merged vectorized RoPE (q+k); V transpose
    rope_qk8<<<(BT * 20 * 8 + 255) / 256, 256>>>(qkvh, rc, rs, qh, kh);
    vtrans_h<<<dim3(TT/32, KVD/32, BB), dim3(32, 8)>>>(qkvh, vth);

    // Tensor-core causal GQA flash attention (writes g_ah fp16)
    attn_mma<<<dim3(TT/128, NH, BB), 256, ATTN_SMEM>>>();

    // Output projection (fp32 output to d_out)
    gemm_f16<false><<<dim3(HIDN/256, BT/128), 256, GEMM_SMEM>>>(ah, woh, out, BT, HIDN, QD);
}